// round 16
// baseline (speedup 1.0000x reference)
#include <cuda_runtime.h>
#include <cuda_bf16.h>
#include <cstdint>

#define D_MODEL 768
#define D3      2304
#define DFF     3072
#define NHEAD   12
#define SEQ     4096
#define BATCH   2
#define MROWS   (BATCH*SEQ)   // 8192

// ------------------------- scratch (device globals; no runtime alloc) -----
__device__ float          g_y [MROWS * D_MODEL];
__device__ float          g_x [MROWS * D_MODEL];
__device__ __nv_bfloat16  g_srcb[MROWS * D_MODEL];
__device__ __nv_bfloat16  g_qkvb[MROWS * D3];
__device__ __nv_bfloat16  g_ctxb[MROWS * D_MODEL];
__device__ __nv_bfloat16  g_xb  [MROWS * D_MODEL];
__device__ __nv_bfloat16  g_hb  [MROWS * DFF];
__device__ __nv_bfloat16  g_wqkvb[D3 * D_MODEL];
__device__ __nv_bfloat16  g_woutb[D_MODEL * D_MODEL];
__device__ __nv_bfloat16  g_w1b  [DFF * D_MODEL];
__device__ __nv_bfloat16  g_w2b  [D_MODEL * DFF];

// ------------------------- helpers ---------------------------------------
__device__ __forceinline__ uint32_t pack2(float lo, float hi) {
    uint32_t r;
    asm("cvt.rn.bf16x2.f32 %0, %2, %1;" : "=r"(r) : "f"(lo), "f"(hi));
    return r;
}

__device__ __forceinline__ uint32_t mulbf2(uint32_t a, uint32_t b) {
    uint32_t r;
    asm("mul.rn.bf16x2 %0, %1, %2;" : "=r"(r) : "r"(a), "r"(b));
    return r;
}

__device__ __forceinline__ void mma_bf16(float* c, const uint32_t* a, const uint32_t* b) {
    asm volatile(
        "mma.sync.aligned.m16n8k16.row.col.f32.bf16.bf16.f32 "
        "{%0,%1,%2,%3},{%4,%5,%6,%7},{%8,%9},{%0,%1,%2,%3};"
        : "+f"(c[0]), "+f"(c[1]), "+f"(c[2]), "+f"(c[3])
        : "r"(a[0]), "r"(a[1]), "r"(a[2]), "r"(a[3]), "r"(b[0]), "r"(b[1]));
}

__device__ __forceinline__ uint32_t su32(const void* p) {
    return (uint32_t)__cvta_generic_to_shared(p);
}

__device__ __forceinline__ void cpa16(uint32_t dst, const void* src) {
    asm volatile("cp.async.cg.shared.global [%0], [%1], 16;" :: "r"(dst), "l"(src));
}
#define CP_COMMIT() asm volatile("cp.async.commit_group;" ::: "memory")
#define CP_WAIT0()  asm volatile("cp.async.wait_group 0;" ::: "memory")

__device__ __forceinline__ void ldsm4(uint32_t* r, uint32_t addr) {
    asm volatile(
        "ldmatrix.sync.aligned.m8n8.x4.shared.b16 {%0,%1,%2,%3}, [%4];"
        : "=r"(r[0]), "=r"(r[1]), "=r"(r[2]), "=r"(r[3]) : "r"(addr));
}

__device__ __forceinline__ void ldsm4t(uint32_t* r, uint32_t addr) {
    asm volatile(
        "ldmatrix.sync.aligned.m8n8.x4.trans.shared.b16 {%0,%1,%2,%3}, [%4];"
        : "=r"(r[0]), "=r"(r[1]), "=r"(r[2]), "=r"(r[3]) : "r"(addr));
}

// ------------------------- fused fp32 -> bf16 convert (all 5 tensors) -----
#define N4_SRC  (MROWS * D_MODEL / 4)
#define N4_WQKV (D3 * D_MODEL / 4)
#define N4_WOUT (D_MODEL * D_MODEL / 4)
#define N4_W1   (DFF * D_MODEL / 4)
#define N4_W2   (D_MODEL * DFF / 4)
#define N4_ALL  (N4_SRC + N4_WQKV + N4_WOUT + N4_W1 + N4_W2)

__global__ __launch_bounds__(256) void f2b_all(
    const float* __restrict__ s_src, const float* __restrict__ s_wqkv,
    const float* __restrict__ s_wout, const float* __restrict__ s_w1,
    const float* __restrict__ s_w2,
    uint32_t* __restrict__ d_src, uint32_t* __restrict__ d_wqkv,
    uint32_t* __restrict__ d_wout, uint32_t* __restrict__ d_w1,
    uint32_t* __restrict__ d_w2)
{
    int i = blockIdx.x * blockDim.x + threadIdx.x;
    if (i >= N4_ALL) return;
    const float* s; uint32_t* d; int j = i;
    if (j < N4_SRC)                    { s = s_src;  d = d_src;  }
    else if ((j -= N4_SRC) < N4_WQKV)  { s = s_wqkv; d = d_wqkv; }
    else if ((j -= N4_WQKV) < N4_WOUT) { s = s_wout; d = d_wout; }
    else if ((j -= N4_WOUT) < N4_W1)   { s = s_w1;   d = d_w1;   }
    else { j -= N4_W1;                   s = s_w2;   d = d_w2;   }
    float4 v = ((const float4*)s)[j];
    d[2 * j]     = pack2(v.x, v.y);
    d[2 * j + 1] = pack2(v.z, v.w);
}

// ------------------------- BF16 GEMM: BK=64, ldmatrix, cp.async (R13) -----
#define GPW 36                       // words per row (32 data + 4 pad)
#define GSTG (128 * GPW)             // words per matrix per stage
#define GEMM_SMEM (4 * GSTG * 4)     // 73728 bytes

__global__ __launch_bounds__(256, 2) void gemm_tc(
    const __nv_bfloat16* __restrict__ A, const __nv_bfloat16* __restrict__ W,
    const float* __restrict__ bias, const float* __restrict__ res,
    float* __restrict__ Cf, __nv_bfloat16* __restrict__ Cb,
    int M, int N, int K, int relu)
{
    extern __shared__ uint32_t gsm[];
    const uint32_t sbase = su32(gsm);

    const int tid  = threadIdx.x;
    const int warp = tid >> 5;
    const int lane = tid & 31;
    const int g = lane >> 2;
    const int t = lane & 3;
    const int wm = warp >> 2;
    const int wn = warp & 3;

    const int bm0 = blockIdx.y * 128;
    const int bn0 = blockIdx.x * 128;

    const int r    = tid >> 1;
    const int half = tid & 1;
    const __nv_bfloat16* Ap = A + (size_t)(bm0 + r) * K + half * 32;
    const __nv_bfloat16* Wp = W + (size_t)(bn0 + r) * K + half * 32;
    const uint32_t dA = sbase + (r * GPW + half * 16) * 4;
    const uint32_t dB = sbase + (2 * GSTG + r * GPW + half * 16) * 4;

    const int arow  = lane & 15;
    const int aword = (lane >> 4) << 2;
    const int brow  = (lane & 7) + ((lane & 16) ? 8 : 0);
    const int bword = (lane & 8) ? 4 : 0;
    const uint32_t aoff = sbase + ((wm * 64 + arow) * GPW + aword) * 4;
    const uint32_t boff = sbase + (2 * GSTG + (wn * 32 + brow) * GPW + bword) * 4;

    float acc[4][4][4];
#pragma unroll
    for (int i = 0; i < 4; ++i)
#pragma unroll
        for (int j = 0; j < 4; ++j)
#pragma unroll
            for (int c = 0; c < 4; ++c) acc[i][j][c] = 0.f;

    const int NT = K / 64;

#pragma unroll
    for (int c = 0; c < 4; ++c) {
        cpa16(dA + c * 16, Ap + c * 8);
        cpa16(dB + c * 16, Wp + c * 8);
    }
    CP_COMMIT();

    for (int it = 0; it < NT; ++it) {
        CP_WAIT0();
        __syncthreads();
        if (it + 1 < NT) {
            const int kc = (it + 1) * 64;
            const uint32_t so = (uint32_t)(((it + 1) & 1) * GSTG * 4);
#pragma unroll
            for (int c = 0; c < 4; ++c) {
                cpa16(dA + so + c * 16, Ap + kc + c * 8);
                cpa16(dB + so + c * 16, Wp + kc + c * 8);
            }
            CP_COMMIT();
        }
        const uint32_t abase = aoff + (uint32_t)((it & 1) * GSTG * 4);
        const uint32_t bbase = boff + (uint32_t)((it & 1) * GSTG * 4);
#pragma unroll
        for (int ks = 0; ks < 4; ++ks) {
            const int kd = ks * 8;
            uint32_t af[4][4], bfr[2][4];
#pragma unroll
            for (int mt = 0; mt < 4; ++mt)
                ldsm4(af[mt], abase + (mt * 16 * GPW + kd) * 4);
#pragma unroll
            for (int p = 0; p < 2; ++p)
                ldsm4(bfr[p], bbase + (p * 16 * GPW + kd) * 4);
#pragma unroll
            for (int mt = 0; mt < 4; ++mt)
#pragma unroll
                for (int nt = 0; nt < 4; ++nt)
                    mma_bf16(acc[mt][nt], af[mt], &bfr[nt >> 1][(nt & 1) * 2]);
        }
    }

#pragma unroll
    for (int nt = 0; nt < 4; ++nt) {
        const int n = bn0 + wn * 32 + nt * 8 + 2 * t;
        const float2 bv = *(const float2*)(bias + n);
#pragma unroll
        for (int mt = 0; mt < 4; ++mt) {
            const int r0 = bm0 + wm * 64 + mt * 16 + g;
            const int r1 = r0 + 8;
            float2 v0 = make_float2(acc[mt][nt][0] + bv.x, acc[mt][nt][1] + bv.y);
            float2 v1 = make_float2(acc[mt][nt][2] + bv.x, acc[mt][nt][3] + bv.y);
            if (res) {
                float2 p0 = *(const float2*)(res + (size_t)r0 * N + n);
                float2 p1 = *(const float2*)(res + (size_t)r1 * N + n);
                v0.x += p0.x; v0.y += p0.y; v1.x += p1.x; v1.y += p1.y;
            }
            if (relu) {
                v0.x = fmaxf(v0.x, 0.f); v0.y = fmaxf(v0.y, 0.f);
                v1.x = fmaxf(v1.x, 0.f); v1.y = fmaxf(v1.y, 0.f);
            }
            if (Cf) {
                *(float2*)(Cf + (size_t)r0 * N + n) = v0;
                *(float2*)(Cf + (size_t)r1 * N + n) = v1;
            }
            if (Cb) {
                *(uint32_t*)(Cb + (size_t)r0 * N + n) = pack2(v0.x, v0.y);
                *(uint32_t*)(Cb + (size_t)r1 * N + n) = pack2(v1.x, v1.y);
            }
        }
    }
}

// ------------------------- BF16 flash attention (register FA-2) -----------
// __launch_bounds__(256,2): force <=128 regs -> 2 CTAs/SM so softmax
// dependency chains are covered by the co-resident CTA's mma work.
#define AW   36
#define KSTG (64 * AW)
#define ATTN_SMEM (4 * KSTG * 4)   // 36864 bytes

__global__ __launch_bounds__(256, 2) void attn_tc(
    const __nv_bfloat16* __restrict__ qkv, __nv_bfloat16* __restrict__ ctx)
{
    extern __shared__ uint32_t smu[];
    const int tid  = threadIdx.x;
    const int lane = tid & 31;
    const int warp = tid >> 5;            // 0..7
    const int g = lane >> 2;
    const int t = lane & 3;
    const int q0w = warp * 16;

    const int bh = blockIdx.y;
    const int b = bh / NHEAD, h = bh % NHEAD;
    const int q0 = blockIdx.x * 128;
    const __nv_bfloat16* Qg = qkv + ((size_t)(b * SEQ + q0)) * D3 + h * 64;
    const __nv_bfloat16* Kg = qkv + ((size_t)(b * SEQ)) * D3 + D_MODEL + h * 64;
    const __nv_bfloat16* Vg = Kg + D_MODEL;

    const int ar = tid >> 2;
    const int ac = (tid & 3) * 2;
    const uint32_t kdst = su32(smu) + (ar * AW + ac * 4) * 4;
    const uint32_t vdst = su32(smu) + (2 * KSTG + ar * AW + ac * 4) * 4;
    const __nv_bfloat16* Ksrc = Kg + (size_t)ar * D3 + ac * 8;
    const __nv_bfloat16* Vsrc = Vg + (size_t)ar * D3 + ac * 8;

    cpa16(kdst, Ksrc);          cpa16(kdst + 16, Ksrc + 8);
    cpa16(vdst, Vsrc);          cpa16(vdst + 16, Vsrc + 8);
    CP_COMMIT();

    uint32_t qf[4][4];
    {
        const uint32_t sc = 0x3E003E00u;   // bf16x2 {0.125, 0.125}
        const __nv_bfloat16* q_lo = Qg + (size_t)(q0w + g) * D3;
        const __nv_bfloat16* q_hi = Qg + (size_t)(q0w + g + 8) * D3;
#pragma unroll
        for (int ks = 0; ks < 4; ++ks) {
            qf[ks][0] = mulbf2(*(const uint32_t*)(q_lo + 16 * ks + 2 * t), sc);
            qf[ks][1] = mulbf2(*(const uint32_t*)(q_hi + 16 * ks + 2 * t), sc);
            qf[ks][2] = mulbf2(*(const uint32_t*)(q_lo + 16 * ks + 8 + 2 * t), sc);
            qf[ks][3] = mulbf2(*(const uint32_t*)(q_hi + 16 * ks + 8 + 2 * t), sc);
        }
    }

    const int brow = (lane & 7) + ((lane & 16) ? 8 : 0);
    const int bword = (lane & 8) ? 4 : 0;
    const int vrow = (lane & 7) + ((lane & 8) ? 8 : 0);
    const int vcol = (lane & 16) ? 8 : 0;

    float accO[8][4];
#pragma unroll
    for (int i = 0; i < 8; ++i)
#pragma unroll
        for (int j = 0; j < 4; ++j) accO[i][j] = 0.f;
    float m_lo = -1e30f, m_hi = -1e30f, l_lo = 0.f, l_hi = 0.f;

    const int NJT = SEQ / 64;
    for (int jt = 0; jt < NJT; ++jt) {
        CP_WAIT0();
        __syncthreads();
        if (jt + 1 < NJT) {
            const size_t jo = (size_t)(jt + 1) * 64 * D3;
            const uint32_t so = (uint32_t)(((jt + 1) & 1) * KSTG * 4);
            cpa16(kdst + so, Ksrc + jo);      cpa16(kdst + so + 16, Ksrc + jo + 8);
            cpa16(vdst + so, Vsrc + jo);      cpa16(vdst + so + 16, Vsrc + jo + 8);
            CP_COMMIT();
        }
        const uint32_t kb = su32(smu) + ((jt & 1) * KSTG) * 4;
        const uint32_t vb = su32(smu) + ((2 + (jt & 1)) * KSTG) * 4;

        float sacc[8][4];
#pragma unroll
        for (int i = 0; i < 8; ++i)
#pragma unroll
            for (int j = 0; j < 4; ++j) sacc[i][j] = 0.f;
#pragma unroll
        for (int ks = 0; ks < 4; ++ks) {
            const int kd = ks * 8;
            uint32_t bfr[4][4];
#pragma unroll
            for (int p = 0; p < 4; ++p)
                ldsm4(bfr[p], kb + ((p * 16 + brow) * AW + kd + bword) * 4);
#pragma unroll
            for (int nt = 0; nt < 8; ++nt)
                mma_bf16(sacc[nt], qf[ks], &bfr[nt >> 1][(nt & 1) * 2]);
        }

        float tl = -1e30f, th = -1e30f;
#pragma unroll
        for (int nt = 0; nt < 8; ++nt) {
            tl = fmaxf(tl, fmaxf(sacc[nt][0], sacc[nt][1]));
            th = fmaxf(th, fmaxf(sacc[nt][2], sacc[nt][3]));
        }
        tl = fmaxf(tl, __shfl_xor_sync(0xffffffffu, tl, 1));
        tl = fmaxf(tl, __shfl_xor_sync(0xffffffffu, tl, 2));
        th = fmaxf(th, __shfl_xor_sync(0xffffffffu, th, 1));
        th = fmaxf(th, __shfl_xor_sync(0xffffffffu, th, 2));
        const float mx_lo = fmaxf(m_lo, tl);
        const float mx_hi = fmaxf(m_hi, th);
        const float r_lo = __expf(m_lo - mx_lo);
        const float r_hi = __expf(m_hi - mx_hi);
        float s_lo = 0.f, s_hi = 0.f;
#pragma unroll
        for (int nt = 0; nt < 8; ++nt) {
            sacc[nt][0] = __expf(sacc[nt][0] - mx_lo);
            sacc[nt][1] = __expf(sacc[nt][1] - mx_lo);
            sacc[nt][2] = __expf(sacc[nt][2] - mx_hi);
            sacc[nt][3] = __expf(sacc[nt][3] - mx_hi);
            s_lo += sacc[nt][0] + sacc[nt][1];
            s_hi += sacc[nt][2] + sacc[nt][3];
        }
        s_lo += __shfl_xor_sync(0xffffffffu, s_lo, 1);
        s_lo += __shfl_xor_sync(0xffffffffu, s_lo, 2);
        s_hi += __shfl_xor_sync(0xffffffffu, s_hi, 1);
        s_hi += __shfl_xor_sync(0xffffffffu, s_hi, 2);
        l_lo = l_lo * r_lo + s_lo;   m_lo = mx_lo;
        l_hi = l_hi * r_hi + s_hi;   m_hi = mx_hi;

#pragma unroll
        for (int nt = 0; nt < 8; ++nt) {
            accO[nt][0] *= r_lo; accO[nt][1] *= r_lo;
            accO[nt][2] *= r_hi; accO[nt][3] *= r_hi;
        }

#pragma unroll
        for (int c = 0; c < 4; ++c) {
            uint32_t af[4];
            af[0] = pack2(sacc[2 * c][0],     sacc[2 * c][1]);
            af[1] = pack2(sacc[2 * c][2],     sacc[2 * c][3]);
            af[2] = pack2(sacc[2 * c + 1][0], sacc[2 * c + 1][1]);
            af[3] = pack2(sacc[2 * c + 1][2], sacc[2 * c + 1][3]);
#pragma unroll
            for (int halfd = 0; halfd < 4; ++halfd) {
                uint32_t rr[4];
                ldsm4t(rr, vb + ((16 * c + vrow) * AW) * 4 + (halfd * 16 + vcol) * 2);
                mma_bf16(accO[halfd * 2 + 0], af, rr);
                mma_bf16(accO[halfd * 2 + 1], af, rr + 2);
            }
        }
    }

    const float ilo = 1.0f / l_lo;
    const float ihi = 1.0f / l_hi;
    __nv_bfloat16* Og = ctx + ((size_t)(b * SEQ + q0)) * D_MODEL + h * 64;
#pragma unroll
    for (int nt = 0; nt < 8; ++nt) {
        const int d = nt * 8 + 2 * t;
        *(uint32_t*)(Og + (size_t)(q0w + g) * D_MODEL + d) =
            pack2(accO[nt][0] * ilo, accO[nt][1] * ilo);
        *(uint32_t*)(Og + (size_t)(q0w + g + 8) * D_MODEL + d) =
            pack2(accO[nt][2] * ihi, accO[nt][3] * ihi);
    }
}

// ------------------------- row LayerNorm (fp32 out + optional bf16) -------
__global__ __launch_bounds__(256) void ln_kernel(
    const float* __restrict__ y, const float* __restrict__ g,
    const float* __restrict__ be, float* __restrict__ o,
    uint32_t* __restrict__ ob)
{
    const int row = blockIdx.x;
    const float* x = y + (size_t)row * D_MODEL;
    const int t = threadIdx.x;
    float v0 = x[t], v1 = x[t + 256], v2 = x[t + 512];
    float s = v0 + v1 + v2;
    float q = v0 * v0 + v1 * v1 + v2 * v2;
#pragma unroll
    for (int off = 16; off; off >>= 1) {
        s += __shfl_xor_sync(0xffffffffu, s, off);
        q += __shfl_xor_sync(0xffffffffu, q, off);
    }
    __shared__ float ss[8], sq[8];
    __shared__ float s_mu, s_inv;
    int w = t >> 5, l = t & 31;
    if (l == 0) { ss[w] = s; sq[w] = q; }
    __syncthreads();
    if (t == 0) {
        float S = 0.f, Q = 0.f;
#pragma unroll
        for (int i = 0; i < 8; ++i) { S += ss[i]; Q += sq[i]; }
        float mu = S * (1.0f / D_MODEL);
        float var = Q * (1.0f / D_MODEL) - mu * mu;
        s_mu = mu;
        s_inv = rsqrtf(var + 1e-5f);
    }
    __syncthreads();
    const float mu = s_mu, inv = s_inv;
    float* op = o + (size_t)row * D_MODEL;
    op[t]       = (v0 - mu) * inv * g[t]       + be[t];
    op[t + 256] = (v1 - mu) * inv * g[t + 256] + be[t + 256];
    op[t + 512] = (v2 - mu) * inv * g[t + 512] + be[t + 512];
    if (ob) {
        uint32_t* obr = ob + (size_t)row * (D_MODEL / 2);
        {
            const int c = 2 * t;
            float a0 = (x[c] - mu) * inv * g[c] + be[c];
            float a1 = (x[c + 1] - mu) * inv * g[c + 1] + be[c + 1];
            obr[t] = pack2(a0, a1);
        }
        if (t < 128) {
            const int c = 512 + 2 * t;
            float a0 = (x[c] - mu) * inv * g[c] + be[c];
            float a1 = (x[c + 1] - mu) * inv * g[c + 1] + be[c + 1];
            obr[256 + t] = pack2(a0, a1);
        }
    }
}

// ------------------------- launch ----------------------------------------
extern "C" void kernel_launch(void* const* d_in, const int* in_sizes, int n_in,
                              void* d_out, int out_size)
{
    const float* src   = (const float*)d_in[0];
    const float* w_qkv = (const float*)d_in[1];
    const float* b_qkv = (const float*)d_in[2];
    const float* w_out = (const float*)d_in[3];
    const float* b_out = (const float*)d_in[4];
    const float* w1    = (const float*)d_in[5];
    const float* b1    = (const float*)d_in[6];
    const float* w2    = (const float*)d_in[7];
    const float* b2    = (const float*)d_in[8];
    const float* ln1w  = (const float*)d_in[9];
    const float* ln1b  = (const float*)d_in[10];
    const float* ln2w  = (const float*)d_in[11];
    const float* ln2b  = (const float*)d_in[12];
    float* out = (float*)d_out;

    float *y, *x;
    __nv_bfloat16 *srcb, *qkvb, *ctxb, *xb, *hb, *wqkvb, *woutb, *w1b, *w2b;
    cudaGetSymbolAddress((void**)&y,     g_y);
    cudaGetSymbolAddress((void**)&x,     g_x);
    cudaGetSymbolAddress((void**)&srcb,  g_srcb);
    cudaGetSymbolAddress((void**)&qkvb,  g_qkvb);
    cudaGetSymbolAddress((void**)&ctxb,  g_ctxb);
    cudaGetSymbolAddress((void**)&xb,    g_xb);
    cudaGetSymbolAddress((void**)&hb,    g_hb);
    cudaGetSymbolAddress((void**)&wqkvb, g_wqkvb);
    cudaGetSymbolAddress((void**)&woutb, g_woutb);
    cudaGetSymbolAddress((void**)&w1b,   g_w1b);
    cudaGetSymbolAddress((void**)&w2b,   g_w2b);

    cudaFuncSetAttribute(gemm_tc,
                         cudaFuncAttributeMaxDynamicSharedMemorySize, GEMM_SMEM);
    cudaFuncSetAttribute(attn_tc,
                         cudaFuncAttributeMaxDynamicSharedMemorySize, ATTN_SMEM);

    dim3 thr(256);
    // 0) fused one-time bf16 conversions
    f2b_all<<<(N4_ALL + 255) / 256, thr>>>(
        src, w_qkv, w_out, w1, w2,
        (uint32_t*)srcb, (uint32_t*)wqkvb, (uint32_t*)woutb,
        (uint32_t*)w1b, (uint32_t*)w2b);

    // 1) QKV projection -> bf16 qkv
    gemm_tc<<<dim3(D3 / 128, MROWS / 128), thr, GEMM_SMEM>>>(
        srcb, wqkvb, b_qkv, nullptr, nullptr, qkvb, MROWS, D3, D_MODEL, 0);
    // 2) flash attention (Bq=128, register softmax, 2 CTAs/SM) -> bf16 ctx
    attn_tc<<<dim3(SEQ / 128, BATCH * NHEAD), thr, ATTN_SMEM>>>(qkvb, ctxb);
    // 3) out projection + residual(src) -> fp32 y
    gemm_tc<<<dim3(D_MODEL / 128, MROWS / 128), thr, GEMM_SMEM>>>(
        ctxb, woutb, b_out, src, y, nullptr, MROWS, D_MODEL, D_MODEL, 0);
    // 4) LN1 -> fp32 x + bf16 xb
    ln_kernel<<<MROWS, 256>>>(y, ln1w, ln1b, x, (uint32_t*)xb);
    // 5) FFN1 + relu -> bf16 h
    gemm_tc<<<dim3(DFF / 128, MROWS / 128), thr, GEMM_SMEM>>>(
        xb, w1b, b1, nullptr, nullptr, hb, MROWS, DFF, D_MODEL, 1);
    // 6) FFN2 + residual(x) -> fp32 y
    gemm_tc<<<dim3(D_MODEL / 128, MROWS / 128), thr, GEMM_SMEM>>>(
        hb, w2b, b2, x, y, nullptr, MROWS, D_MODEL, DFF, 0);
    // 7) LN2 -> out
    ln_kernel<<<MROWS, 256>>>(y, ln2w, ln2b, out, nullptr);
}